// round 2
// baseline (speedup 1.0000x reference)
#include <cuda_runtime.h>
#include <math.h>

// Fixed problem shapes
#define B_    4
#define IMH   40
#define IMW   160
#define NTOK  6400        // IMH*IMW
#define D_    256
#define NH    8
#define NP    9
#define HDIM  32          // D_/NH
#define MTOT  25600       // B_*NTOK

// Scratch buffers (static device globals -- no runtime allocation allowed)
__device__ float g_q   [(size_t)MTOT * D_];        // (B,N,256)  channel = h*32+d
__device__ float g_kv  [(size_t)MTOT * 2 * D_];    // (B,N,512)  [0:256)=k, [256:512)=v
__device__ float g_off [(size_t)MTOT * NH * NP * 2];// (B,N,144) raw (pre-tanh)
__device__ float g_attn[(size_t)MTOT * D_];        // (B,N,256)  attention output

// ---------------------------------------------------------------------------
// Tiled FP32 SGEMM:  C[M,Nc] = X[M,K] @ W[Nc,K]^T + bias[Nc]
// BM=BN=128, BK=16, 256 threads, 8x8 per thread. M multiple of 128, K mult of 16.
// Nc guarded (handles Nc=144).
// ---------------------------------------------------------------------------
__global__ __launch_bounds__(256, 2) void sgemm_xwT(
    const float* __restrict__ X, const float* __restrict__ W,
    const float* __restrict__ bias, float* __restrict__ C,
    int K, int Nc)
{
    __shared__ float As[16][128];
    __shared__ float Bs[16][128];

    const int tid = threadIdx.x;
    const int bm  = blockIdx.y * 128;
    const int bn  = blockIdx.x * 128;
    const int tx  = tid & 15;   // n direction
    const int ty  = tid >> 4;   // m direction

    float acc[8][8];
#pragma unroll
    for (int i = 0; i < 8; i++)
#pragma unroll
        for (int j = 0; j < 8; j++) acc[i][j] = 0.f;

    for (int kt = 0; kt < K; kt += 16) {
#pragma unroll
        for (int i = 0; i < 2; i++) {
            int idx = tid + i * 256;          // 0..511
            int row = idx >> 2;               // 0..127
            int c4  = (idx & 3) << 2;         // 0,4,8,12
            float4 xv = *reinterpret_cast<const float4*>(
                &X[(size_t)(bm + row) * K + kt + c4]);
            As[c4 + 0][row] = xv.x; As[c4 + 1][row] = xv.y;
            As[c4 + 2][row] = xv.z; As[c4 + 3][row] = xv.w;

            int wrow = bn + row;
            float4 wv = make_float4(0.f, 0.f, 0.f, 0.f);
            if (wrow < Nc)
                wv = *reinterpret_cast<const float4*>(
                    &W[(size_t)wrow * K + kt + c4]);
            Bs[c4 + 0][row] = wv.x; Bs[c4 + 1][row] = wv.y;
            Bs[c4 + 2][row] = wv.z; Bs[c4 + 3][row] = wv.w;
        }
        __syncthreads();

#pragma unroll
        for (int k = 0; k < 16; k++) {
            float a[8], b[8];
#pragma unroll
            for (int i = 0; i < 8; i++) a[i] = As[k][ty * 8 + i];
#pragma unroll
            for (int j = 0; j < 8; j++) b[j] = Bs[k][tx * 8 + j];
#pragma unroll
            for (int i = 0; i < 8; i++)
#pragma unroll
                for (int j = 0; j < 8; j++)
                    acc[i][j] = fmaf(a[i], b[j], acc[i][j]);
        }
        __syncthreads();
    }

#pragma unroll
    for (int i = 0; i < 8; i++) {
        int m = bm + ty * 8 + i;
#pragma unroll
        for (int j = 0; j < 8; j++) {
            int nn = bn + tx * 8 + j;
            if (nn < Nc)
                C[(size_t)m * Nc + nn] = acc[i][j] + bias[nn];
        }
    }
}

// ---------------------------------------------------------------------------
// Deformable sampling + attention. One warp per (b,h,n); lane = channel d.
// Gathers are 128B-coalesced per corner. Softmax over P=9 in registers.
// ---------------------------------------------------------------------------
__global__ __launch_bounds__(256) void deform_attn(
    const float* __restrict__ q, const float* __restrict__ kv,
    const float* __restrict__ offs, float* __restrict__ attn_out)
{
    const int gwarp = (blockIdx.x * blockDim.x + threadIdx.x) >> 5;
    const int lane  = threadIdx.x & 31;
    if (gwarp >= B_ * NH * NTOK) return;

    const int n  = gwarp % NTOK;
    const int bh = gwarp / NTOK;
    const int b  = bh >> 3;
    const int h  = bh & 7;

    const float base_x = (float)(n % IMW);
    const float base_y = (float)(n / IMW);

    const float qd = q[(size_t)(b * NTOK + n) * D_ + h * HDIM + lane];
    const float* offrow = offs + (size_t)(b * NTOK + n) * (NH * NP * 2) + h * (NP * 2);
    const float* kvb = kv + (size_t)b * NTOK * (2 * D_) + h * HDIM + lane;

    float logits[NP];
    float sv[NP];

#pragma unroll
    for (int p = 0; p < NP; p++) {
        float ox = tanhf(offrow[2 * p])     * 4.0f;
        float oy = tanhf(offrow[2 * p + 1]) * 4.0f;
        float sx = base_x + ox;
        float sy = base_y + oy;
        float x0 = floorf(sx), y0 = floorf(sy);
        float wx1 = sx - x0, wy1 = sy - y0;
        float wx0 = 1.f - wx1, wy0 = 1.f - wy1;
        int ix0 = (int)x0, iy0 = (int)y0;

        float sk = 0.f, svp = 0.f;
#pragma unroll
        for (int c = 0; c < 4; c++) {
            int xi = ix0 + (c & 1);
            int yi = iy0 + (c >> 1);
            float wgt = ((c & 1) ? wx1 : wx0) * ((c >> 1) ? wy1 : wy0);
            if (xi >= 0 && xi < IMW && yi >= 0 && yi < IMH) {
                const float* row = kvb + (size_t)(yi * IMW + xi) * (2 * D_);
                sk  = fmaf(wgt, row[0],  sk);
                svp = fmaf(wgt, row[D_], svp);
            }
        }
        // warp-reduce dot(q, sampled_k); butterfly so all lanes get the result
        float part = qd * sk;
#pragma unroll
        for (int o = 16; o; o >>= 1)
            part += __shfl_xor_sync(0xffffffffu, part, o);
        logits[p] = part * 0.17677669529663689f;   // 1/sqrt(32)
        sv[p] = svp;
    }

    // softmax over 9 points (replicated per lane)
    float mx = logits[0];
#pragma unroll
    for (int p = 1; p < NP; p++) mx = fmaxf(mx, logits[p]);
    float ssum = 0.f;
#pragma unroll
    for (int p = 0; p < NP; p++) { logits[p] = __expf(logits[p] - mx); ssum += logits[p]; }
    float inv = 1.f / ssum;

    float outd = 0.f;
#pragma unroll
    for (int p = 0; p < NP; p++) outd = fmaf(logits[p] * inv, sv[p], outd);

    attn_out[(size_t)(b * NTOK + n) * D_ + h * HDIM + lane] = outd;
}

// ---------------------------------------------------------------------------
extern "C" void kernel_launch(void* const* d_in, const int* in_sizes, int n_in,
                              void* d_out, int out_size)
{
    const float* x    = (const float*)d_in[0];
    const float* Wq   = (const float*)d_in[1];
    const float* bq   = (const float*)d_in[2];
    const float* Woff = (const float*)d_in[3];
    const float* boff = (const float*)d_in[4];
    const float* Wkv  = (const float*)d_in[5];
    const float* bkv  = (const float*)d_in[6];
    const float* Wout = (const float*)d_in[7];
    const float* bout = (const float*)d_in[8];
    float* out = (float*)d_out;

    float *qp, *kvp, *offp, *attnp;
    cudaGetSymbolAddress((void**)&qp,    g_q);
    cudaGetSymbolAddress((void**)&kvp,   g_kv);
    cudaGetSymbolAddress((void**)&offp,  g_off);
    cudaGetSymbolAddress((void**)&attnp, g_attn);

    const int K = D_;
    // q = x @ Wq^T + bq            (25600 x 256)
    sgemm_xwT<<<dim3(2, MTOT / 128), 256>>>(x, Wq, bq, qp, K, D_);
    // off_raw = x @ Woff^T + boff  (25600 x 144)
    sgemm_xwT<<<dim3(2, MTOT / 128), 256>>>(x, Woff, boff, offp, K, NH * NP * 2);
    // kv = x @ Wkv^T + bkv         (25600 x 512)
    sgemm_xwT<<<dim3(4, MTOT / 128), 256>>>(x, Wkv, bkv, kvp, K, 2 * D_);

    // deformable sampling + attention: one warp per (b,h,n)
    const int total_warps = B_ * NH * NTOK;            // 204800
    deform_attn<<<(total_warps * 32) / 256, 256>>>(qp, kvp, offp, attnp);

    // out = attn @ Wout^T + bout   (25600 x 256)
    sgemm_xwT<<<dim3(2, MTOT / 128), 256>>>(attnp, Wout, bout, out, K, D_);
}

// round 4
// speedup vs baseline: 1.0418x; 1.0418x over previous
#include <cuda_runtime.h>
#include <math.h>

// Fixed problem shapes
#define B_    4
#define IMH   40
#define IMW   160
#define NTOK  6400        // IMH*IMW
#define D_    256
#define NH    8
#define NP    9
#define HDIM  32          // D_/NH
#define MTOT  25600       // B_*NTOK

// Scratch buffers (static device globals -- no runtime allocation allowed)
__device__ float g_q   [(size_t)MTOT * D_];
__device__ float g_kv  [(size_t)MTOT * 2 * D_];
__device__ float g_off [(size_t)MTOT * NH * NP * 2];
__device__ float g_attn[(size_t)MTOT * D_];

// ---------------------------------------------------------------------------
// Double-buffered FP32 SGEMM:  C[M,Nc] = X[M,K] @ W[Nc,K]^T + bias[Nc]
// BM=BN=128, BK=8, 256 threads, 8x8 per thread, register-staged prefetch.
// M multiple of 128, K multiple of 8. Nc guarded (handles Nc=144).
// ---------------------------------------------------------------------------
__global__ __launch_bounds__(256, 2) void sgemm_xwT(
    const float* __restrict__ X, const float* __restrict__ W,
    const float* __restrict__ bias, float* __restrict__ C,
    int K, int Nc)
{
    __shared__ float As[2][8][128];
    __shared__ float Bs[2][8][128];

    const int tid = threadIdx.x;
    const int bm  = blockIdx.y * 128;
    const int bn  = blockIdx.x * 128;
    const int tx  = tid & 15;   // n direction
    const int ty  = tid >> 4;   // m direction

    // Global-load mapping: 128 rows x 8 cols = 256 float4; 1 per thread/operand.
    const int lrow = tid >> 1;              // 0..127
    const int lc4  = (tid & 1) << 2;        // 0 or 4
    const bool wvalid = (bn + lrow) < Nc;
    const float* Xg = X + (size_t)(bm + lrow) * K + lc4;
    const float* Wg = W + (size_t)(bn + lrow) * K + lc4;

    float acc[8][8];
#pragma unroll
    for (int i = 0; i < 8; i++)
#pragma unroll
        for (int j = 0; j < 8; j++) acc[i][j] = 0.f;

    float4 xr, wr;
    // preload tile 0
    xr = *reinterpret_cast<const float4*>(Xg);
    wr = wvalid ? *reinterpret_cast<const float4*>(Wg)
                : make_float4(0.f, 0.f, 0.f, 0.f);
    As[0][lc4 + 0][lrow] = xr.x; As[0][lc4 + 1][lrow] = xr.y;
    As[0][lc4 + 2][lrow] = xr.z; As[0][lc4 + 3][lrow] = xr.w;
    Bs[0][lc4 + 0][lrow] = wr.x; Bs[0][lc4 + 1][lrow] = wr.y;
    Bs[0][lc4 + 2][lrow] = wr.z; Bs[0][lc4 + 3][lrow] = wr.w;
    __syncthreads();

    const int nt = K >> 3;
    for (int t = 0; t < nt; t++) {
        const int cur = t & 1;
        const int nxt = cur ^ 1;
        if (t + 1 < nt) {
            xr = *reinterpret_cast<const float4*>(Xg + (t + 1) * 8);
            wr = wvalid ? *reinterpret_cast<const float4*>(Wg + (t + 1) * 8)
                        : make_float4(0.f, 0.f, 0.f, 0.f);
        }

#pragma unroll
        for (int k = 0; k < 8; k++) {
            float4 a0 = *reinterpret_cast<const float4*>(&As[cur][k][ty * 8]);
            float4 a1 = *reinterpret_cast<const float4*>(&As[cur][k][ty * 8 + 4]);
            float4 b0 = *reinterpret_cast<const float4*>(&Bs[cur][k][tx * 8]);
            float4 b1 = *reinterpret_cast<const float4*>(&Bs[cur][k][tx * 8 + 4]);
            float a[8] = {a0.x, a0.y, a0.z, a0.w, a1.x, a1.y, a1.z, a1.w};
            float b[8] = {b0.x, b0.y, b0.z, b0.w, b1.x, b1.y, b1.z, b1.w};
#pragma unroll
            for (int i = 0; i < 8; i++)
#pragma unroll
                for (int j = 0; j < 8; j++)
                    acc[i][j] = fmaf(a[i], b[j], acc[i][j]);
        }

        if (t + 1 < nt) {
            As[nxt][lc4 + 0][lrow] = xr.x; As[nxt][lc4 + 1][lrow] = xr.y;
            As[nxt][lc4 + 2][lrow] = xr.z; As[nxt][lc4 + 3][lrow] = xr.w;
            Bs[nxt][lc4 + 0][lrow] = wr.x; Bs[nxt][lc4 + 1][lrow] = wr.y;
            Bs[nxt][lc4 + 2][lrow] = wr.z; Bs[nxt][lc4 + 3][lrow] = wr.w;
            __syncthreads();
        }
    }

#pragma unroll
    for (int i = 0; i < 8; i++) {
        int m = bm + ty * 8 + i;
#pragma unroll
        for (int j = 0; j < 8; j++) {
            int nn = bn + tx * 8 + j;
            if (nn < Nc)
                C[(size_t)m * Nc + nn] = acc[i][j] + bias[nn];
        }
    }
}

// ---------------------------------------------------------------------------
__device__ __forceinline__ float tanh_fast(float x) {
    float y;
    asm("tanh.approx.f32 %0, %1;" : "=f"(y) : "f"(x));
    return y;
}

// Deformable sampling + attention. One warp per (b,h,n); lane = channel d.
__global__ __launch_bounds__(256) void deform_attn(
    const float* __restrict__ q, const float* __restrict__ kv,
    const float* __restrict__ offs, float* __restrict__ attn_out)
{
    const int gwarp = (blockIdx.x * blockDim.x + threadIdx.x) >> 5;
    const int lane  = threadIdx.x & 31;
    if (gwarp >= B_ * NH * NTOK) return;

    const int n  = gwarp % NTOK;
    const int bh = gwarp / NTOK;
    const int b  = bh >> 3;
    const int h  = bh & 7;

    const float base_x = (float)(n % IMW);
    const float base_y = (float)(n / IMW);

    const float qd = q[(size_t)(b * NTOK + n) * D_ + h * HDIM + lane];
    const float* offrow = offs + (size_t)(b * NTOK + n) * (NH * NP * 2) + h * (NP * 2);
    const float* kvb = kv + (size_t)b * NTOK * (2 * D_) + h * HDIM + lane;

    float logits[NP];
    float sv[NP];

#pragma unroll
    for (int p = 0; p < NP; p++) {
        float ox = tanh_fast(offrow[2 * p])     * 4.0f;
        float oy = tanh_fast(offrow[2 * p + 1]) * 4.0f;
        float sx = base_x + ox;
        float sy = base_y + oy;
        float x0 = floorf(sx), y0 = floorf(sy);
        float wx1 = sx - x0, wy1 = sy - y0;
        float wx0 = 1.f - wx1, wy0 = 1.f - wy1;
        int ix0 = (int)x0, iy0 = (int)y0;

        float sk = 0.f, svp = 0.f;
#pragma unroll
        for (int c = 0; c < 4; c++) {
            int xi = ix0 + (c & 1);
            int yi = iy0 + (c >> 1);
            float wgt = ((c & 1) ? wx1 : wx0) * ((c >> 1) ? wy1 : wy0);
            if (xi >= 0 && xi < IMW && yi >= 0 && yi < IMH) {
                const float* row = kvb + (size_t)(yi * IMW + xi) * (2 * D_);
                sk  = fmaf(wgt, row[0],  sk);
                svp = fmaf(wgt, row[D_], svp);
            }
        }
        float part = qd * sk;
#pragma unroll
        for (int o = 16; o; o >>= 1)
            part += __shfl_xor_sync(0xffffffffu, part, o);
        logits[p] = part * 0.17677669529663689f;   // 1/sqrt(32)
        sv[p] = svp;
    }

    float mx = logits[0];
#pragma unroll
    for (int p = 1; p < NP; p++) mx = fmaxf(mx, logits[p]);
    float ssum = 0.f;
#pragma unroll
    for (int p = 0; p < NP; p++) { logits[p] = __expf(logits[p] - mx); ssum += logits[p]; }
    float inv = __fdividef(1.f, ssum);

    float outd = 0.f;
#pragma unroll
    for (int p = 0; p < NP; p++) outd = fmaf(logits[p] * inv, sv[p], outd);

    attn_out[(size_t)(b * NTOK + n) * D_ + h * HDIM + lane] = outd;
}

// ---------------------------------------------------------------------------
extern "C" void kernel_launch(void* const* d_in, const int* in_sizes, int n_in,
                              void* d_out, int out_size)
{
    const float* x    = (const float*)d_in[0];
    const float* Wq   = (const float*)d_in[1];
    const float* bq   = (const float*)d_in[2];
    const float* Woff = (const float*)d_in[3];
    const float* boff = (const float*)d_in[4];
    const float* Wkv  = (const float*)d_in[5];
    const float* bkv  = (const float*)d_in[6];
    const float* Wout = (const float*)d_in[7];
    const float* bout = (const float*)d_in[8];
    float* out = (float*)d_out;

    float *qp, *kvp, *offp, *attnp;
    cudaGetSymbolAddress((void**)&qp,    g_q);
    cudaGetSymbolAddress((void**)&kvp,   g_kv);
    cudaGetSymbolAddress((void**)&offp,  g_off);
    cudaGetSymbolAddress((void**)&attnp, g_attn);

    const int K = D_;
    sgemm_xwT<<<dim3(2, MTOT / 128), 256>>>(x, Wq, bq, qp, K, D_);
    sgemm_xwT<<<dim3(2, MTOT / 128), 256>>>(x, Woff, boff, offp, K, NH * NP * 2);
    sgemm_xwT<<<dim3(4, MTOT / 128), 256>>>(x, Wkv, bkv, kvp, K, 2 * D_);

    const int total_warps = B_ * NH * NTOK;            // 204800
    deform_attn<<<(total_warps * 32) / 256, 256>>>(qp, kvp, offp, attnp);

    sgemm_xwT<<<dim3(2, MTOT / 128), 256>>>(attnp, Wout, bout, out, K, D_);
}

// round 10
// speedup vs baseline: 1.6410x; 1.5751x over previous
#include <cuda_runtime.h>
#include <math.h>

// Fixed problem shapes
#define B_    4
#define IMH   40
#define IMW   160
#define NTOK  6400
#define D_    256
#define NH    8
#define NP    9
#define HDIM  32
#define MTOT  25600

__device__ float g_q   [(size_t)MTOT * D_];
__device__ float g_kv  [(size_t)MTOT * 2 * D_];
__device__ float g_off [(size_t)MTOT * NH * NP * 2];
__device__ float g_attn[(size_t)MTOT * D_];

// ---------------------------------------------------------------------------
// TF32 tensor-core GEMM: C[M,Nc] = X[M,K] @ W[Nc,K]^T + bias  (Nc mult of 128,
// M mult of 128, K mult of 16). mma.sync.m16n8k8.tf32, 128x128 block, 8 warps,
// 64x32 warp tile, BK=16 double-buffered.
// ---------------------------------------------------------------------------
#define SPAD 20

__device__ __forceinline__ unsigned f2tf32(float f) {
    unsigned u;
    asm("cvt.rna.tf32.f32 %0, %1;" : "=r"(u) : "f"(f));
    return u;
}

__global__ __launch_bounds__(256) void gemm_tf32(
    const float* __restrict__ X, const float* __restrict__ W,
    const float* __restrict__ bias, float* __restrict__ C,
    int K, int Nc)
{
    __shared__ unsigned As[2][128][SPAD];
    __shared__ unsigned Bs[2][128][SPAD];

    const int tid    = threadIdx.x;
    const int lane   = tid & 31;
    const int wid    = tid >> 5;
    const int warp_m = wid >> 2;          // 0..1  -> 64-row slab
    const int warp_n = wid & 3;           // 0..3  -> 32-col slab
    const int g      = lane >> 2;         // 0..7
    const int t      = lane & 3;          // 0..3

    const int bm = blockIdx.y * 128;
    const int bn = blockIdx.x * 128;

    // global-load map: 2 float4 per thread per operand per stage
    const int r0  = tid >> 1;                   // 0..127
    const int c40 = (tid & 1) << 2;             // 0 or 4
    const float* Xg = X + (size_t)(bm + r0) * K + c40;
    const float* Wg = W + (size_t)(bn + r0) * K + c40;

    float acc[4][4][4];
#pragma unroll
    for (int i = 0; i < 4; i++)
#pragma unroll
        for (int j = 0; j < 4; j++)
#pragma unroll
            for (int c = 0; c < 4; c++) acc[i][j][c] = 0.f;

    // preload stage 0
    float4 xr0 = *reinterpret_cast<const float4*>(Xg);
    float4 xr1 = *reinterpret_cast<const float4*>(Xg + 8);
    float4 wr0 = *reinterpret_cast<const float4*>(Wg);
    float4 wr1 = *reinterpret_cast<const float4*>(Wg + 8);
    {
        unsigned* a = &As[0][r0][c40];
        a[0]=f2tf32(xr0.x); a[1]=f2tf32(xr0.y); a[2]=f2tf32(xr0.z); a[3]=f2tf32(xr0.w);
        a[8]=f2tf32(xr1.x); a[9]=f2tf32(xr1.y); a[10]=f2tf32(xr1.z); a[11]=f2tf32(xr1.w);
        unsigned* b = &Bs[0][r0][c40];
        b[0]=f2tf32(wr0.x); b[1]=f2tf32(wr0.y); b[2]=f2tf32(wr0.z); b[3]=f2tf32(wr0.w);
        b[8]=f2tf32(wr1.x); b[9]=f2tf32(wr1.y); b[10]=f2tf32(wr1.z); b[11]=f2tf32(wr1.w);
    }
    __syncthreads();

    const int nstg = K >> 4;       // 16 for K=256
    for (int s = 0; s < nstg; s++) {
        const int cur = s & 1;
        const int nxt = cur ^ 1;
        if (s + 1 < nstg) {
            const int ko = (s + 1) << 4;
            xr0 = *reinterpret_cast<const float4*>(Xg + ko);
            xr1 = *reinterpret_cast<const float4*>(Xg + ko + 8);
            wr0 = *reinterpret_cast<const float4*>(Wg + ko);
            wr1 = *reinterpret_cast<const float4*>(Wg + ko + 8);
        }

#pragma unroll
        for (int kb = 0; kb < 16; kb += 8) {
            unsigned af[4][4], bf[4][2];
#pragma unroll
            for (int mt = 0; mt < 4; mt++) {
                const int r = warp_m * 64 + mt * 16 + g;
                af[mt][0] = As[cur][r    ][kb + t];
                af[mt][1] = As[cur][r + 8][kb + t];
                af[mt][2] = As[cur][r    ][kb + t + 4];
                af[mt][3] = As[cur][r + 8][kb + t + 4];
            }
#pragma unroll
            for (int nt = 0; nt < 4; nt++) {
                const int c = warp_n * 32 + nt * 8 + g;
                bf[nt][0] = Bs[cur][c][kb + t];
                bf[nt][1] = Bs[cur][c][kb + t + 4];
            }
#pragma unroll
            for (int mt = 0; mt < 4; mt++)
#pragma unroll
                for (int nt = 0; nt < 4; nt++) {
                    float* cc = acc[mt][nt];
                    asm volatile(
                        "mma.sync.aligned.m16n8k8.row.col.f32.tf32.tf32.f32 "
                        "{%0,%1,%2,%3}, {%4,%5,%6,%7}, {%8,%9}, {%0,%1,%2,%3};"
                        : "+f"(cc[0]), "+f"(cc[1]), "+f"(cc[2]), "+f"(cc[3])
                        : "r"(af[mt][0]), "r"(af[mt][1]), "r"(af[mt][2]), "r"(af[mt][3]),
                          "r"(bf[nt][0]), "r"(bf[nt][1]));
                }
        }

        if (s + 1 < nstg) {
            unsigned* a = &As[nxt][r0][c40];
            a[0]=f2tf32(xr0.x); a[1]=f2tf32(xr0.y); a[2]=f2tf32(xr0.z); a[3]=f2tf32(xr0.w);
            a[8]=f2tf32(xr1.x); a[9]=f2tf32(xr1.y); a[10]=f2tf32(xr1.z); a[11]=f2tf32(xr1.w);
            unsigned* b = &Bs[nxt][r0][c40];
            b[0]=f2tf32(wr0.x); b[1]=f2tf32(wr0.y); b[2]=f2tf32(wr0.z); b[3]=f2tf32(wr0.w);
            b[8]=f2tf32(wr1.x); b[9]=f2tf32(wr1.y); b[10]=f2tf32(wr1.z); b[11]=f2tf32(wr1.w);
            __syncthreads();
        }
    }

    // epilogue
#pragma unroll
    for (int mt = 0; mt < 4; mt++) {
        const int row0 = bm + warp_m * 64 + mt * 16 + g;
#pragma unroll
        for (int nt = 0; nt < 4; nt++) {
            const int col = bn + warp_n * 32 + nt * 8 + 2 * t;
            const float b0 = __ldg(&bias[col]);
            const float b1 = __ldg(&bias[col + 1]);
            float2 v0 = make_float2(acc[mt][nt][0] + b0, acc[mt][nt][1] + b1);
            float2 v1 = make_float2(acc[mt][nt][2] + b0, acc[mt][nt][3] + b1);
            *reinterpret_cast<float2*>(&C[(size_t)row0 * Nc + col]) = v0;
            *reinterpret_cast<float2*>(&C[(size_t)(row0 + 8) * Nc + col]) = v1;
        }
    }
}

// ---------------------------------------------------------------------------
// FP32 SGEMM (kept for the offsets projection, Nc=144 -- precision-sensitive)
// ---------------------------------------------------------------------------
__global__ __launch_bounds__(256, 2) void sgemm_xwT(
    const float* __restrict__ X, const float* __restrict__ W,
    const float* __restrict__ bias, float* __restrict__ C,
    int K, int Nc)
{
    __shared__ float As[2][8][128];
    __shared__ float Bs[2][8][128];

    const int tid = threadIdx.x;
    const int bm  = blockIdx.y * 128;
    const int bn  = blockIdx.x * 128;
    const int tx  = tid & 15;
    const int ty  = tid >> 4;

    const int lrow = tid >> 1;
    const int lc4  = (tid & 1) << 2;
    const bool wvalid = (bn + lrow) < Nc;
    const float* Xg = X + (size_t)(bm + lrow) * K + lc4;
    const float* Wg = W + (size_t)(bn + lrow) * K + lc4;

    float acc[8][8];
#pragma unroll
    for (int i = 0; i < 8; i++)
#pragma unroll
        for (int j = 0; j < 8; j++) acc[i][j] = 0.f;

    float4 xr, wr;
    xr = *reinterpret_cast<const float4*>(Xg);
    wr = wvalid ? *reinterpret_cast<const float4*>(Wg)
                : make_float4(0.f, 0.f, 0.f, 0.f);
    As[0][lc4 + 0][lrow] = xr.x; As[0][lc4 + 1][lrow] = xr.y;
    As[0][lc4 + 2][lrow] = xr.z; As[0][lc4 + 3][lrow] = xr.w;
    Bs[0][lc4 + 0][lrow] = wr.x; Bs[0][lc4 + 1][lrow] = wr.y;
    Bs[0][lc4 + 2][lrow] = wr.z; Bs[0][lc4 + 3][lrow] = wr.w;
    __syncthreads();

    const int nt = K >> 3;
    for (int t = 0; t < nt; t++) {
        const int cur = t & 1;
        const int nxt = cur ^ 1;
        if (t + 1 < nt) {
            xr = *reinterpret_cast<const float4*>(Xg + (t + 1) * 8);
            wr = wvalid ? *reinterpret_cast<const float4*>(Wg + (t + 1) * 8)
                        : make_float4(0.f, 0.f, 0.f, 0.f);
        }

#pragma unroll
        for (int k = 0; k < 8; k++) {
            float4 a0 = *reinterpret_cast<const float4*>(&As[cur][k][ty * 8]);
            float4 a1 = *reinterpret_cast<const float4*>(&As[cur][k][ty * 8 + 4]);
            float4 b0 = *reinterpret_cast<const float4*>(&Bs[cur][k][tx * 8]);
            float4 b1 = *reinterpret_cast<const float4*>(&Bs[cur][k][tx * 8 + 4]);
            float a[8] = {a0.x, a0.y, a0.z, a0.w, a1.x, a1.y, a1.z, a1.w};
            float b[8] = {b0.x, b0.y, b0.z, b0.w, b1.x, b1.y, b1.z, b1.w};
#pragma unroll
            for (int i = 0; i < 8; i++)
#pragma unroll
                for (int j = 0; j < 8; j++)
                    acc[i][j] = fmaf(a[i], b[j], acc[i][j]);
        }

        if (t + 1 < nt) {
            As[nxt][lc4 + 0][lrow] = xr.x; As[nxt][lc4 + 1][lrow] = xr.y;
            As[nxt][lc4 + 2][lrow] = xr.z; As[nxt][lc4 + 3][lrow] = xr.w;
            Bs[nxt][lc4 + 0][lrow] = wr.x; Bs[nxt][lc4 + 1][lrow] = wr.y;
            Bs[nxt][lc4 + 2][lrow] = wr.z; Bs[nxt][lc4 + 3][lrow] = wr.w;
            __syncthreads();
        }
    }

#pragma unroll
    for (int i = 0; i < 8; i++) {
        int m = bm + ty * 8 + i;
#pragma unroll
        for (int j = 0; j < 8; j++) {
            int nn = bn + tx * 8 + j;
            if (nn < Nc)
                C[(size_t)m * Nc + nn] = acc[i][j] + bias[nn];
        }
    }
}

// ---------------------------------------------------------------------------
__device__ __forceinline__ float tanh_fast(float x) {
    float y;
    asm("tanh.approx.f32 %0, %1;" : "=f"(y) : "f"(x));
    return y;
}

__global__ __launch_bounds__(256) void deform_attn(
    const float* __restrict__ q, const float* __restrict__ kv,
    const float* __restrict__ offs, float* __restrict__ attn_out)
{
    const int gwarp = (blockIdx.x * blockDim.x + threadIdx.x) >> 5;
    const int lane  = threadIdx.x & 31;
    if (gwarp >= B_ * NH * NTOK) return;

    const int n  = gwarp % NTOK;
    const int bh = gwarp / NTOK;
    const int b  = bh >> 3;
    const int h  = bh & 7;

    const float base_x = (float)(n % IMW);
    const float base_y = (float)(n / IMW);

    const float qd = q[(size_t)(b * NTOK + n) * D_ + h * HDIM + lane];
    const float* offrow = offs + (size_t)(b * NTOK + n) * (NH * NP * 2) + h * (NP * 2);
    const float* kvb = kv + (size_t)b * NTOK * (2 * D_) + h * HDIM + lane;

    float logits[NP];
    float sv[NP];

#pragma unroll
    for (int p = 0; p < NP; p++) {
        float ox = tanh_fast(offrow[2 * p])     * 4.0f;
        float oy = tanh_fast(offrow[2 * p + 1]) * 4.0f;
        float sx = base_x + ox;
        float sy = base_y + oy;
        float x0 = floorf(sx), y0 = floorf(sy);
        float wx1 = sx - x0, wy1 = sy - y0;
        float wx0 = 1.f - wx1, wy0 = 1.f - wy1;
        int ix0 = (int)x0, iy0 = (int)y0;

        float sk = 0.f, svp = 0.f;
#pragma unroll
        for (int c = 0; c < 4; c++) {
            int xi = ix0 + (c & 1);
            int yi = iy0 + (c >> 1);
            float wgt = ((c & 1) ? wx1 : wx0) * ((c >> 1) ? wy1 : wy0);
            if (xi >= 0 && xi < IMW && yi >= 0 && yi < IMH) {
                const float* row = kvb + (size_t)(yi * IMW + xi) * (2 * D_);
                sk  = fmaf(wgt, row[0],  sk);
                svp = fmaf(wgt, row[D_], svp);
            }
        }
        float part = qd * sk;
#pragma unroll
        for (int o = 16; o; o >>= 1)
            part += __shfl_xor_sync(0xffffffffu, part, o);
        logits[p] = part * 0.17677669529663689f;
        sv[p] = svp;
    }

    float mx = logits[0];
#pragma unroll
    for (int p = 1; p < NP; p++) mx = fmaxf(mx, logits[p]);
    float ssum = 0.f;
#pragma unroll
    for (int p = 0; p < NP; p++) { logits[p] = __expf(logits[p] - mx); ssum += logits[p]; }
    float inv = __fdividef(1.f, ssum);

    float outd = 0.f;
#pragma unroll
    for (int p = 0; p < NP; p++) outd = fmaf(logits[p] * inv, sv[p], outd);

    attn_out[(size_t)(b * NTOK + n) * D_ + h * HDIM + lane] = outd;
}

// ---------------------------------------------------------------------------
extern "C" void kernel_launch(void* const* d_in, const int* in_sizes, int n_in,
                              void* d_out, int out_size)
{
    const float* x    = (const float*)d_in[0];
    const float* Wq   = (const float*)d_in[1];
    const float* bq   = (const float*)d_in[2];
    const float* Woff = (const float*)d_in[3];
    const float* boff = (const float*)d_in[4];
    const float* Wkv  = (const float*)d_in[5];
    const float* bkv  = (const float*)d_in[6];
    const float* Wout = (const float*)d_in[7];
    const float* bout = (const float*)d_in[8];
    float* out = (float*)d_out;

    float *qp, *kvp, *offp, *attnp;
    cudaGetSymbolAddress((void**)&qp,    g_q);
    cudaGetSymbolAddress((void**)&kvp,   g_kv);
    cudaGetSymbolAddress((void**)&offp,  g_off);
    cudaGetSymbolAddress((void**)&attnp, g_attn);

    const int K = D_;
    // q = x @ Wq^T + bq (tf32 tensor cores)
    gemm_tf32<<<dim3(2, MTOT / 128), 256>>>(x, Wq, bq, qp, K, D_);
    // offsets = x @ Woff^T + boff (fp32 -- precision-sensitive path)
    sgemm_xwT<<<dim3(2, MTOT / 128), 256>>>(x, Woff, boff, offp, K, NH * NP * 2);
    // kv = x @ Wkv^T + bkv (tf32)
    gemm_tf32<<<dim3(4, MTOT / 128), 256>>>(x, Wkv, bkv, kvp, K, 2 * D_);

    const int total_warps = B_ * NH * NTOK;
    deform_attn<<<(total_warps * 32) / 256, 256>>>(qp, kvp, offp, attnp);

    // out = attn @ Wout^T + bout (tf32)
    gemm_tf32<<<dim3(2, MTOT / 128), 256>>>(attnp, Wout, bout, out, K, D_);
}

// round 11
// speedup vs baseline: 1.6714x; 1.0185x over previous
#include <cuda_runtime.h>
#include <math.h>

// Fixed problem shapes
#define B_    4
#define IMH   40
#define IMW   160
#define NTOK  6400
#define D_    256
#define NH    8
#define NP    9
#define HDIM  32
#define MTOT  25600

__device__ float g_q   [(size_t)MTOT * D_];
__device__ float g_kv  [(size_t)MTOT * 2 * D_];   // interleaved: (k_c, v_c) float2 pairs
__device__ float g_off [(size_t)MTOT * NH * NP * 2];
__device__ float g_attn[(size_t)MTOT * D_];

// ---------------------------------------------------------------------------
// TF32 tensor-core GEMM: C[M,Nc] = X[M,K] @ W[Nc,K]^T + bias
// interleave_kv: Nc=512; col<256 -> k channel col, col>=256 -> v channel col-256;
// stored as C[row*512 + ch*2 + isV] so (k,v) for a channel are adjacent.
// ---------------------------------------------------------------------------
#define SPAD 20

__device__ __forceinline__ unsigned f2tf32(float f) {
    unsigned u;
    asm("cvt.rna.tf32.f32 %0, %1;" : "=r"(u) : "f"(f));
    return u;
}

__global__ __launch_bounds__(256) void gemm_tf32(
    const float* __restrict__ X, const float* __restrict__ W,
    const float* __restrict__ bias, float* __restrict__ C,
    int K, int Nc, int interleave_kv)
{
    __shared__ unsigned As[2][128][SPAD];
    __shared__ unsigned Bs[2][128][SPAD];

    const int tid    = threadIdx.x;
    const int lane   = tid & 31;
    const int wid    = tid >> 5;
    const int warp_m = wid >> 2;
    const int warp_n = wid & 3;
    const int g      = lane >> 2;
    const int t      = lane & 3;

    const int bm = blockIdx.y * 128;
    const int bn = blockIdx.x * 128;

    const int r0  = tid >> 1;
    const int c40 = (tid & 1) << 2;
    const float* Xg = X + (size_t)(bm + r0) * K + c40;
    const float* Wg = W + (size_t)(bn + r0) * K + c40;

    float acc[4][4][4];
#pragma unroll
    for (int i = 0; i < 4; i++)
#pragma unroll
        for (int j = 0; j < 4; j++)
#pragma unroll
            for (int c = 0; c < 4; c++) acc[i][j][c] = 0.f;

    float4 xr0 = *reinterpret_cast<const float4*>(Xg);
    float4 xr1 = *reinterpret_cast<const float4*>(Xg + 8);
    float4 wr0 = *reinterpret_cast<const float4*>(Wg);
    float4 wr1 = *reinterpret_cast<const float4*>(Wg + 8);
    {
        unsigned* a = &As[0][r0][c40];
        a[0]=f2tf32(xr0.x); a[1]=f2tf32(xr0.y); a[2]=f2tf32(xr0.z); a[3]=f2tf32(xr0.w);
        a[8]=f2tf32(xr1.x); a[9]=f2tf32(xr1.y); a[10]=f2tf32(xr1.z); a[11]=f2tf32(xr1.w);
        unsigned* b = &Bs[0][r0][c40];
        b[0]=f2tf32(wr0.x); b[1]=f2tf32(wr0.y); b[2]=f2tf32(wr0.z); b[3]=f2tf32(wr0.w);
        b[8]=f2tf32(wr1.x); b[9]=f2tf32(wr1.y); b[10]=f2tf32(wr1.z); b[11]=f2tf32(wr1.w);
    }
    __syncthreads();

    const int nstg = K >> 4;
    for (int s = 0; s < nstg; s++) {
        const int cur = s & 1;
        const int nxt = cur ^ 1;
        if (s + 1 < nstg) {
            const int ko = (s + 1) << 4;
            xr0 = *reinterpret_cast<const float4*>(Xg + ko);
            xr1 = *reinterpret_cast<const float4*>(Xg + ko + 8);
            wr0 = *reinterpret_cast<const float4*>(Wg + ko);
            wr1 = *reinterpret_cast<const float4*>(Wg + ko + 8);
        }

#pragma unroll
        for (int kb = 0; kb < 16; kb += 8) {
            unsigned af[4][4], bf[4][2];
#pragma unroll
            for (int mt = 0; mt < 4; mt++) {
                const int r = warp_m * 64 + mt * 16 + g;
                af[mt][0] = As[cur][r    ][kb + t];
                af[mt][1] = As[cur][r + 8][kb + t];
                af[mt][2] = As[cur][r    ][kb + t + 4];
                af[mt][3] = As[cur][r + 8][kb + t + 4];
            }
#pragma unroll
            for (int nt = 0; nt < 4; nt++) {
                const int c = warp_n * 32 + nt * 8 + g;
                bf[nt][0] = Bs[cur][c][kb + t];
                bf[nt][1] = Bs[cur][c][kb + t + 4];
            }
#pragma unroll
            for (int mt = 0; mt < 4; mt++)
#pragma unroll
                for (int nt = 0; nt < 4; nt++) {
                    float* cc = acc[mt][nt];
                    asm volatile(
                        "mma.sync.aligned.m16n8k8.row.col.f32.tf32.tf32.f32 "
                        "{%0,%1,%2,%3}, {%4,%5,%6,%7}, {%8,%9}, {%0,%1,%2,%3};"
                        : "+f"(cc[0]), "+f"(cc[1]), "+f"(cc[2]), "+f"(cc[3])
                        : "r"(af[mt][0]), "r"(af[mt][1]), "r"(af[mt][2]), "r"(af[mt][3]),
                          "r"(bf[nt][0]), "r"(bf[nt][1]));
                }
        }

        if (s + 1 < nstg) {
            unsigned* a = &As[nxt][r0][c40];
            a[0]=f2tf32(xr0.x); a[1]=f2tf32(xr0.y); a[2]=f2tf32(xr0.z); a[3]=f2tf32(xr0.w);
            a[8]=f2tf32(xr1.x); a[9]=f2tf32(xr1.y); a[10]=f2tf32(xr1.z); a[11]=f2tf32(xr1.w);
            unsigned* b = &Bs[nxt][r0][c40];
            b[0]=f2tf32(wr0.x); b[1]=f2tf32(wr0.y); b[2]=f2tf32(wr0.z); b[3]=f2tf32(wr0.w);
            b[8]=f2tf32(wr1.x); b[9]=f2tf32(wr1.y); b[10]=f2tf32(wr1.z); b[11]=f2tf32(wr1.w);
            __syncthreads();
        }
    }

    // epilogue
    const int isV   = (interleave_kv && bn >= 256) ? 1 : 0;
    const int choff = isV ? 256 : 0;
#pragma unroll
    for (int mt = 0; mt < 4; mt++) {
        const int row0 = bm + warp_m * 64 + mt * 16 + g;
#pragma unroll
        for (int nt = 0; nt < 4; nt++) {
            const int col = bn + warp_n * 32 + nt * 8 + 2 * t;
            const float b0 = __ldg(&bias[col]);
            const float b1 = __ldg(&bias[col + 1]);
            float c00 = acc[mt][nt][0] + b0, c01 = acc[mt][nt][1] + b1;
            float c10 = acc[mt][nt][2] + b0, c11 = acc[mt][nt][3] + b1;
            if (!interleave_kv) {
                *reinterpret_cast<float2*>(&C[(size_t)row0 * Nc + col]) =
                    make_float2(c00, c01);
                *reinterpret_cast<float2*>(&C[(size_t)(row0 + 8) * Nc + col]) =
                    make_float2(c10, c11);
            } else {
                const int ch = col - choff;                  // 0..254 (even)
                size_t p0 = (size_t)row0 * 512 + ch * 2 + isV;
                size_t p1 = (size_t)(row0 + 8) * 512 + ch * 2 + isV;
                C[p0] = c00; C[p0 + 2] = c01;
                C[p1] = c10; C[p1 + 2] = c11;
            }
        }
    }
}

// ---------------------------------------------------------------------------
// FP32 SGEMM (offsets projection, Nc=144 -- precision-sensitive)
// ---------------------------------------------------------------------------
__global__ __launch_bounds__(256, 2) void sgemm_xwT(
    const float* __restrict__ X, const float* __restrict__ W,
    const float* __restrict__ bias, float* __restrict__ C,
    int K, int Nc)
{
    __shared__ float As[2][8][128];
    __shared__ float Bs[2][8][128];

    const int tid = threadIdx.x;
    const int bm  = blockIdx.y * 128;
    const int bn  = blockIdx.x * 128;
    const int tx  = tid & 15;
    const int ty  = tid >> 4;

    const int lrow = tid >> 1;
    const int lc4  = (tid & 1) << 2;
    const bool wvalid = (bn + lrow) < Nc;
    const float* Xg = X + (size_t)(bm + lrow) * K + lc4;
    const float* Wg = W + (size_t)(bn + lrow) * K + lc4;

    float acc[8][8];
#pragma unroll
    for (int i = 0; i < 8; i++)
#pragma unroll
        for (int j = 0; j < 8; j++) acc[i][j] = 0.f;

    float4 xr, wr;
    xr = *reinterpret_cast<const float4*>(Xg);
    wr = wvalid ? *reinterpret_cast<const float4*>(Wg)
                : make_float4(0.f, 0.f, 0.f, 0.f);
    As[0][lc4 + 0][lrow] = xr.x; As[0][lc4 + 1][lrow] = xr.y;
    As[0][lc4 + 2][lrow] = xr.z; As[0][lc4 + 3][lrow] = xr.w;
    Bs[0][lc4 + 0][lrow] = wr.x; Bs[0][lc4 + 1][lrow] = wr.y;
    Bs[0][lc4 + 2][lrow] = wr.z; Bs[0][lc4 + 3][lrow] = wr.w;
    __syncthreads();

    const int nt = K >> 3;
    for (int t = 0; t < nt; t++) {
        const int cur = t & 1;
        const int nxt = cur ^ 1;
        if (t + 1 < nt) {
            xr = *reinterpret_cast<const float4*>(Xg + (t + 1) * 8);
            wr = wvalid ? *reinterpret_cast<const float4*>(Wg + (t + 1) * 8)
                        : make_float4(0.f, 0.f, 0.f, 0.f);
        }

#pragma unroll
        for (int k = 0; k < 8; k++) {
            float4 a0 = *reinterpret_cast<const float4*>(&As[cur][k][ty * 8]);
            float4 a1 = *reinterpret_cast<const float4*>(&As[cur][k][ty * 8 + 4]);
            float4 b0 = *reinterpret_cast<const float4*>(&Bs[cur][k][tx * 8]);
            float4 b1 = *reinterpret_cast<const float4*>(&Bs[cur][k][tx * 8 + 4]);
            float a[8] = {a0.x, a0.y, a0.z, a0.w, a1.x, a1.y, a1.z, a1.w};
            float b[8] = {b0.x, b0.y, b0.z, b0.w, b1.x, b1.y, b1.z, b1.w};
#pragma unroll
            for (int i = 0; i < 8; i++)
#pragma unroll
                for (int j = 0; j < 8; j++)
                    acc[i][j] = fmaf(a[i], b[j], acc[i][j]);
        }

        if (t + 1 < nt) {
            As[nxt][lc4 + 0][lrow] = xr.x; As[nxt][lc4 + 1][lrow] = xr.y;
            As[nxt][lc4 + 2][lrow] = xr.z; As[nxt][lc4 + 3][lrow] = xr.w;
            Bs[nxt][lc4 + 0][lrow] = wr.x; Bs[nxt][lc4 + 1][lrow] = wr.y;
            Bs[nxt][lc4 + 2][lrow] = wr.z; Bs[nxt][lc4 + 3][lrow] = wr.w;
            __syncthreads();
        }
    }

#pragma unroll
    for (int i = 0; i < 8; i++) {
        int m = bm + ty * 8 + i;
#pragma unroll
        for (int j = 0; j < 8; j++) {
            int nn = bn + tx * 8 + j;
            if (nn < Nc)
                C[(size_t)m * Nc + nn] = acc[i][j] + bias[nn];
        }
    }
}

// ---------------------------------------------------------------------------
__device__ __forceinline__ float tanh_fast(float x) {
    float y;
    asm("tanh.approx.f32 %0, %1;" : "=f"(y) : "f"(x));
    return y;
}

// Deformable sampling + attention. One warp per (b,h,n); lane = channel d.
// kv is interleaved (k,v) float2 per channel -> one LDG.64 per corner.
// Offsets/tanh computed lane-parallel (lane p handles point p), broadcast via shfl.
__global__ __launch_bounds__(256) void deform_attn(
    const float* __restrict__ q, const float2* __restrict__ kv2,
    const float* __restrict__ offs, float* __restrict__ attn_out)
{
    const int gwarp = (blockIdx.x * blockDim.x + threadIdx.x) >> 5;
    const int lane  = threadIdx.x & 31;
    if (gwarp >= B_ * NH * NTOK) return;

    const int n  = gwarp % NTOK;
    const int bh = gwarp / NTOK;
    const int b  = bh >> 3;
    const int h  = bh & 7;

    const float qd = q[(size_t)(b * NTOK + n) * D_ + h * HDIM + lane];
    const float2* kvb = kv2 + (size_t)b * NTOK * D_ + h * HDIM + lane;

    // lane-parallel offset computation: lane p computes sample point p
    float sxl = 0.f, syl = 0.f;
    if (lane < NP) {
        const float* offrow = offs + (size_t)(b * NTOK + n) * (NH * NP * 2)
                            + h * (NP * 2) + 2 * lane;
        float ox = tanh_fast(offrow[0]) * 4.0f;
        float oy = tanh_fast(offrow[1]) * 4.0f;
        sxl = (float)(n % IMW) + ox;
        syl = (float)(n / IMW) + oy;
    }

    float logits[NP];
    float sv[NP];

#pragma unroll
    for (int p = 0; p < NP; p++) {
        const float sx = __shfl_sync(0xffffffffu, sxl, p);
        const float sy = __shfl_sync(0xffffffffu, syl, p);
        float x0 = floorf(sx), y0 = floorf(sy);
        float wx1 = sx - x0, wy1 = sy - y0;
        float wx0 = 1.f - wx1, wy0 = 1.f - wy1;
        int ix0 = (int)x0, iy0 = (int)y0;

        float sk = 0.f, svp = 0.f;
#pragma unroll
        for (int c = 0; c < 4; c++) {
            int xi = ix0 + (c & 1);
            int yi = iy0 + (c >> 1);
            float wgt = ((c & 1) ? wx1 : wx0) * ((c >> 1) ? wy1 : wy0);
            if (xi >= 0 && xi < IMW && yi >= 0 && yi < IMH) {
                float2 kvv = kvb[(size_t)(yi * IMW + xi) * D_];
                sk  = fmaf(wgt, kvv.x, sk);
                svp = fmaf(wgt, kvv.y, svp);
            }
        }
        float part = qd * sk;
#pragma unroll
        for (int o = 16; o; o >>= 1)
            part += __shfl_xor_sync(0xffffffffu, part, o);
        logits[p] = part * 0.17677669529663689f;
        sv[p] = svp;
    }

    float mx = logits[0];
#pragma unroll
    for (int p = 1; p < NP; p++) mx = fmaxf(mx, logits[p]);
    float ssum = 0.f;
#pragma unroll
    for (int p = 0; p < NP; p++) { logits[p] = __expf(logits[p] - mx); ssum += logits[p]; }
    float inv = __fdividef(1.f, ssum);

    float outd = 0.f;
#pragma unroll
    for (int p = 0; p < NP; p++) outd = fmaf(logits[p] * inv, sv[p], outd);

    attn_out[(size_t)(b * NTOK + n) * D_ + h * HDIM + lane] = outd;
}

// ---------------------------------------------------------------------------
extern "C" void kernel_launch(void* const* d_in, const int* in_sizes, int n_in,
                              void* d_out, int out_size)
{
    const float* x    = (const float*)d_in[0];
    const float* Wq   = (const float*)d_in[1];
    const float* bq   = (const float*)d_in[2];
    const float* Woff = (const float*)d_in[3];
    const float* boff = (const float*)d_in[4];
    const float* Wkv  = (const float*)d_in[5];
    const float* bkv  = (const float*)d_in[6];
    const float* Wout = (const float*)d_in[7];
    const float* bout = (const float*)d_in[8];
    float* out = (float*)d_out;

    float *qp, *kvp, *offp, *attnp;
    cudaGetSymbolAddress((void**)&qp,    g_q);
    cudaGetSymbolAddress((void**)&kvp,   g_kv);
    cudaGetSymbolAddress((void**)&offp,  g_off);
    cudaGetSymbolAddress((void**)&attnp, g_attn);

    const int K = D_;
    // q = x @ Wq^T + bq (tf32)
    gemm_tf32<<<dim3(2, MTOT / 128), 256>>>(x, Wq, bq, qp, K, D_, 0);
    // offsets = x @ Woff^T + boff (fp32 -- precision-sensitive)
    sgemm_xwT<<<dim3(2, MTOT / 128), 256>>>(x, Woff, boff, offp, K, NH * NP * 2);
    // kv = x @ Wkv^T + bkv (tf32, interleaved (k,v) epilogue)
    gemm_tf32<<<dim3(4, MTOT / 128), 256>>>(x, Wkv, bkv, kvp, K, 2 * D_, 1);

    const int total_warps = B_ * NH * NTOK;
    deform_attn<<<(total_warps * 32) / 256, 256>>>(
        qp, (const float2*)kvp, offp, attnp);

    // out = attn @ Wout^T + bout (tf32)
    gemm_tf32<<<dim3(2, MTOT / 128), 256>>>(attnp, Wout, bout, out, K, D_, 0);
}

// round 16
// speedup vs baseline: 1.7335x; 1.0371x over previous
#include <cuda_runtime.h>
#include <math.h>

// Fixed problem shapes
#define B_    4
#define IMH   40
#define IMW   160
#define NTOK  6400
#define D_    256
#define NH    8
#define NP    9
#define HDIM  32
#define MTOT  25600

__device__ float g_q   [(size_t)MTOT * D_];
__device__ float g_kv  [(size_t)MTOT * 2 * D_];   // interleaved: (k_c, v_c) float2 pairs
__device__ float g_off [(size_t)MTOT * NH * NP * 2];
__device__ float g_attn[(size_t)MTOT * D_];

// ---------------------------------------------------------------------------
// TF32 tensor-core GEMM: C[M,Nc] = X[M,K] @ W[Nc,K]^T + bias
// Smem k-dim is permuted within each 8-block (phys = 2*(k&3) + ((k>>2)&1))
// so each thread's (t, t+4) fragment pair is one LDS.64.
// ---------------------------------------------------------------------------
#define SPAD 20

__device__ __forceinline__ unsigned f2tf32(float f) {
    unsigned u;
    asm("cvt.rna.tf32.f32 %0, %1;" : "=r"(u) : "f"(f));
    return u;
}

__global__ __launch_bounds__(256) void gemm_tf32(
    const float* __restrict__ X, const float* __restrict__ W,
    const float* __restrict__ bias, float* __restrict__ C,
    int K, int Nc, int interleave_kv)
{
    __shared__ __align__(16) unsigned As[2][128][SPAD];
    __shared__ __align__(16) unsigned Bs[2][128][SPAD];

    const int tid    = threadIdx.x;
    const int lane   = tid & 31;
    const int wid    = tid >> 5;
    const int warp_m = wid >> 2;
    const int warp_n = wid & 3;
    const int g      = lane >> 2;
    const int t      = lane & 3;

    const int bm = blockIdx.y * 128;
    const int bn = blockIdx.x * 128;

    const int r0  = tid >> 1;
    const int c40 = (tid & 1) << 2;       // 0 or 4 (logical k base of this thread's float4)
    const int po  = c40 >> 2;             // 0 or 1: physical parity offset
    const float* Xg = X + (size_t)(bm + r0) * K + c40;
    const float* Wg = W + (size_t)(bn + r0) * K + c40;

    float acc[4][4][4];
#pragma unroll
    for (int i = 0; i < 4; i++)
#pragma unroll
        for (int j = 0; j < 4; j++)
#pragma unroll
            for (int c = 0; c < 4; c++) acc[i][j][c] = 0.f;

    float4 xr0, xr1, wr0, wr1;

    // permuted smem store: logical k -> phys (k&8) + 2*(k&3) + ((k>>2)&1)
#define STORE_STAGE(st)                                                        \
    do {                                                                       \
        unsigned* a = &As[st][r0][po];                                         \
        a[0]=f2tf32(xr0.x); a[2]=f2tf32(xr0.y); a[4]=f2tf32(xr0.z); a[6]=f2tf32(xr0.w); \
        a[8]=f2tf32(xr1.x); a[10]=f2tf32(xr1.y); a[12]=f2tf32(xr1.z); a[14]=f2tf32(xr1.w); \
        unsigned* b = &Bs[st][r0][po];                                         \
        b[0]=f2tf32(wr0.x); b[2]=f2tf32(wr0.y); b[4]=f2tf32(wr0.z); b[6]=f2tf32(wr0.w); \
        b[8]=f2tf32(wr1.x); b[10]=f2tf32(wr1.y); b[12]=f2tf32(wr1.z); b[14]=f2tf32(wr1.w); \
    } while (0)

    xr0 = *reinterpret_cast<const float4*>(Xg);
    xr1 = *reinterpret_cast<const float4*>(Xg + 8);
    wr0 = *reinterpret_cast<const float4*>(Wg);
    wr1 = *reinterpret_cast<const float4*>(Wg + 8);
    STORE_STAGE(0);
    __syncthreads();

    const int nstg = K >> 4;
    for (int s = 0; s < nstg; s++) {
        const int cur = s & 1;
        const int nxt = cur ^ 1;
        if (s + 1 < nstg) {
            const int ko = (s + 1) << 4;
            xr0 = *reinterpret_cast<const float4*>(Xg + ko);
            xr1 = *reinterpret_cast<const float4*>(Xg + ko + 8);
            wr0 = *reinterpret_cast<const float4*>(Wg + ko);
            wr1 = *reinterpret_cast<const float4*>(Wg + ko + 8);
        }

#pragma unroll
        for (int kb = 0; kb < 16; kb += 8) {
            // vectorized fragment loads: phys (kb+2t, kb+2t+1) = logical (kb+t, kb+t+4)
            uint2 av0[4], av1[4], bv[4];
#pragma unroll
            for (int mt = 0; mt < 4; mt++) {
                const int r = warp_m * 64 + mt * 16 + g;
                av0[mt] = *reinterpret_cast<const uint2*>(&As[cur][r    ][kb + 2 * t]);
                av1[mt] = *reinterpret_cast<const uint2*>(&As[cur][r + 8][kb + 2 * t]);
            }
#pragma unroll
            for (int nt = 0; nt < 4; nt++) {
                const int c = warp_n * 32 + nt * 8 + g;
                bv[nt] = *reinterpret_cast<const uint2*>(&Bs[cur][c][kb + 2 * t]);
            }
#pragma unroll
            for (int mt = 0; mt < 4; mt++)
#pragma unroll
                for (int nt = 0; nt < 4; nt++) {
                    float* cc = acc[mt][nt];
                    asm volatile(
                        "mma.sync.aligned.m16n8k8.row.col.f32.tf32.tf32.f32 "
                        "{%0,%1,%2,%3}, {%4,%5,%6,%7}, {%8,%9}, {%0,%1,%2,%3};"
                        : "+f"(cc[0]), "+f"(cc[1]), "+f"(cc[2]), "+f"(cc[3])
                        : "r"(av0[mt].x), "r"(av1[mt].x), "r"(av0[mt].y), "r"(av1[mt].y),
                          "r"(bv[nt].x), "r"(bv[nt].y));
                }
        }

        if (s + 1 < nstg) {
            STORE_STAGE(nxt);
            __syncthreads();
        }
    }
#undef STORE_STAGE

    // epilogue
    const int isV   = (interleave_kv && bn >= 256) ? 1 : 0;
    const int choff = isV ? 256 : 0;
#pragma unroll
    for (int mt = 0; mt < 4; mt++) {
        const int row0 = bm + warp_m * 64 + mt * 16 + g;
#pragma unroll
        for (int nt = 0; nt < 4; nt++) {
            const int col = bn + warp_n * 32 + nt * 8 + 2 * t;
            const float b0 = __ldg(&bias[col]);
            const float b1 = __ldg(&bias[col + 1]);
            float c00 = acc[mt][nt][0] + b0, c01 = acc[mt][nt][1] + b1;
            float c10 = acc[mt][nt][2] + b0, c11 = acc[mt][nt][3] + b1;
            if (!interleave_kv) {
                *reinterpret_cast<float2*>(&C[(size_t)row0 * Nc + col]) =
                    make_float2(c00, c01);
                *reinterpret_cast<float2*>(&C[(size_t)(row0 + 8) * Nc + col]) =
                    make_float2(c10, c11);
            } else {
                const int ch = col - choff;
                size_t p0 = (size_t)row0 * 512 + ch * 2 + isV;
                size_t p1 = (size_t)(row0 + 8) * 512 + ch * 2 + isV;
                C[p0] = c00; C[p0 + 2] = c01;
                C[p1] = c10; C[p1 + 2] = c11;
            }
        }
    }
}

// ---------------------------------------------------------------------------
// FP32 SGEMM (offsets projection, Nc=144 -- precision-sensitive)
// ---------------------------------------------------------------------------
__global__ __launch_bounds__(256, 2) void sgemm_xwT(
    const float* __restrict__ X, const float* __restrict__ W,
    const float* __restrict__ bias, float* __restrict__ C,
    int K, int Nc)
{
    __shared__ float As[2][8][128];
    __shared__ float Bs[2][8][128];

    const int tid = threadIdx.x;
    const int bm  = blockIdx.y * 128;
    const int bn  = blockIdx.x * 128;
    const int tx  = tid & 15;
    const int ty  = tid >> 4;

    const int lrow = tid >> 1;
    const int lc4  = (tid & 1) << 2;
    const bool wvalid = (bn + lrow) < Nc;
    const float* Xg = X + (size_t)(bm + lrow) * K + lc4;
    const float* Wg = W + (size_t)(bn + lrow) * K + lc4;

    float acc[8][8];
#pragma unroll
    for (int i = 0; i < 8; i++)
#pragma unroll
        for (int j = 0; j < 8; j++) acc[i][j] = 0.f;

    float4 xr, wr;
    xr = *reinterpret_cast<const float4*>(Xg);
    wr = wvalid ? *reinterpret_cast<const float4*>(Wg)
                : make_float4(0.f, 0.f, 0.f, 0.f);
    As[0][lc4 + 0][lrow] = xr.x; As[0][lc4 + 1][lrow] = xr.y;
    As[0][lc4 + 2][lrow] = xr.z; As[0][lc4 + 3][lrow] = xr.w;
    Bs[0][lc4 + 0][lrow] = wr.x; Bs[0][lc4 + 1][lrow] = wr.y;
    Bs[0][lc4 + 2][lrow] = wr.z; Bs[0][lc4 + 3][lrow] = wr.w;
    __syncthreads();

    const int nt = K >> 3;
    for (int t = 0; t < nt; t++) {
        const int cur = t & 1;
        const int nxt = cur ^ 1;
        if (t + 1 < nt) {
            xr = *reinterpret_cast<const float4*>(Xg + (t + 1) * 8);
            wr = wvalid ? *reinterpret_cast<const float4*>(Wg + (t + 1) * 8)
                        : make_float4(0.f, 0.f, 0.f, 0.f);
        }

#pragma unroll
        for (int k = 0; k < 8; k++) {
            float4 a0 = *reinterpret_cast<const float4*>(&As[cur][k][ty * 8]);
            float4 a1 = *reinterpret_cast<const float4*>(&As[cur][k][ty * 8 + 4]);
            float4 b0 = *reinterpret_cast<const float4*>(&Bs[cur][k][tx * 8]);
            float4 b1 = *reinterpret_cast<const float4*>(&Bs[cur][k][tx * 8 + 4]);
            float a[8] = {a0.x, a0.y, a0.z, a0.w, a1.x, a1.y, a1.z, a1.w};
            float b[8] = {b0.x, b0.y, b0.z, b0.w, b1.x, b1.y, b1.z, b1.w};
#pragma unroll
            for (int i = 0; i < 8; i++)
#pragma unroll
                for (int j = 0; j < 8; j++)
                    acc[i][j] = fmaf(a[i], b[j], acc[i][j]);
        }

        if (t + 1 < nt) {
            As[nxt][lc4 + 0][lrow] = xr.x; As[nxt][lc4 + 1][lrow] = xr.y;
            As[nxt][lc4 + 2][lrow] = xr.z; As[nxt][lc4 + 3][lrow] = xr.w;
            Bs[nxt][lc4 + 0][lrow] = wr.x; Bs[nxt][lc4 + 1][lrow] = wr.y;
            Bs[nxt][lc4 + 2][lrow] = wr.z; Bs[nxt][lc4 + 3][lrow] = wr.w;
            __syncthreads();
        }
    }

#pragma unroll
    for (int i = 0; i < 8; i++) {
        int m = bm + ty * 8 + i;
#pragma unroll
        for (int j = 0; j < 8; j++) {
            int nn = bn + tx * 8 + j;
            if (nn < Nc)
                C[(size_t)m * Nc + nn] = acc[i][j] + bias[nn];
        }
    }
}

// ---------------------------------------------------------------------------
__device__ __forceinline__ float tanh_fast(float x) {
    float y;
    asm("tanh.approx.f32 %0, %1;" : "=f"(y) : "f"(x));
    return y;
}

// butterfly all-lanes warp sum (redux.sync.f32 is not in the sm_103 ISA)
__device__ __forceinline__ float warp_sum(float x) {
#pragma unroll
    for (int o = 16; o; o >>= 1)
        x += __shfl_xor_sync(0xffffffffu, x, o);
    return x;
}

// Deformable sampling + attention. One warp per (b,h,n); lane = channel d.
// kv interleaved (k,v) float2 per channel. Offsets lane-parallel + shfl bcast.
// Warp-uniform fast path for interior points.
__global__ __launch_bounds__(256) void deform_attn(
    const float* __restrict__ q, const float2* __restrict__ kv2,
    const float* __restrict__ offs, float* __restrict__ attn_out)
{
    const int gwarp = (blockIdx.x * blockDim.x + threadIdx.x) >> 5;
    const int lane  = threadIdx.x & 31;
    if (gwarp >= B_ * NH * NTOK) return;

    const int n  = gwarp % NTOK;
    const int bh = gwarp / NTOK;
    const int b  = bh >> 3;
    const int h  = bh & 7;

    const float qd = q[(size_t)(b * NTOK + n) * D_ + h * HDIM + lane]
                   * 0.17677669529663689f;   // fold 1/sqrt(32) into q
    const float2* kvb = kv2 + (size_t)b * NTOK * D_ + h * HDIM + lane;

    // lane-parallel offsets: lane p computes sample point p
    float sxl = 0.f, syl = 0.f;
    if (lane < NP) {
        const float* offrow = offs + (size_t)(b * NTOK + n) * (NH * NP * 2)
                            + h * (NP * 2) + 2 * lane;
        sxl = (float)(n % IMW) + tanh_fast(offrow[0]) * 4.0f;
        syl = (float)(n / IMW) + tanh_fast(offrow[1]) * 4.0f;
    }

    float logits[NP];
    float sv[NP];

#pragma unroll
    for (int p = 0; p < NP; p++) {
        const float sx = __shfl_sync(0xffffffffu, sxl, p);
        const float sy = __shfl_sync(0xffffffffu, syl, p);
        float x0 = floorf(sx), y0 = floorf(sy);
        float wx1 = sx - x0, wy1 = sy - y0;
        float wx0 = 1.f - wx1, wy0 = 1.f - wy1;
        int ix0 = (int)x0, iy0 = (int)y0;

        float sk, svp;
        if (ix0 >= 0 && iy0 >= 0 && ix0 < IMW - 1 && iy0 < IMH - 1) {
            // interior fast path: all 4 corners valid (warp-uniform branch)
            const size_t base = (size_t)(iy0 * IMW + ix0) * D_;
            float2 v00 = kvb[base];
            float2 v01 = kvb[base + D_];
            float2 v10 = kvb[base + IMW * D_];
            float2 v11 = kvb[base + IMW * D_ + D_];
            float w00 = wx0 * wy0, w01 = wx1 * wy0;
            float w10 = wx0 * wy1, w11 = wx1 * wy1;
            sk  = fmaf(w00, v00.x, fmaf(w01, v01.x, fmaf(w10, v10.x, w11 * v11.x)));
            svp = fmaf(w00, v00.y, fmaf(w01, v01.y, fmaf(w10, v10.y, w11 * v11.y)));
        } else {
            sk = 0.f; svp = 0.f;
#pragma unroll
            for (int c = 0; c < 4; c++) {
                int xi = ix0 + (c & 1);
                int yi = iy0 + (c >> 1);
                float wgt = ((c & 1) ? wx1 : wx0) * ((c >> 1) ? wy1 : wy0);
                if (xi >= 0 && xi < IMW && yi >= 0 && yi < IMH) {
                    float2 kvv = kvb[(size_t)(yi * IMW + xi) * D_];
                    sk  = fmaf(wgt, kvv.x, sk);
                    svp = fmaf(wgt, kvv.y, svp);
                }
            }
        }
        logits[p] = warp_sum(qd * sk);
        sv[p] = svp;
    }

    float mx = logits[0];
#pragma unroll
    for (int p = 1; p < NP; p++) mx = fmaxf(mx, logits[p]);
    float ssum = 0.f;
#pragma unroll
    for (int p = 0; p < NP; p++) { logits[p] = __expf(logits[p] - mx); ssum += logits[p]; }
    float inv = __fdividef(1.f, ssum);

    float outd = 0.f;
#pragma unroll
    for (int p = 0; p < NP; p++) outd = fmaf(logits[p] * inv, sv[p], outd);

    attn_out[(size_t)(b * NTOK + n) * D_ + h * HDIM + lane] = outd;
}

// ---------------------------------------------------------------------------
extern "C" void kernel_launch(void* const* d_in, const int* in_sizes, int n_in,
                              void* d_out, int out_size)
{
    const float* x    = (const float*)d_in[0];
    const float* Wq   = (const float*)d_in[1];
    const float* bq   = (const float*)d_in[2];
    const float* Woff = (const float*)d_in[3];
    const float* boff = (const float*)d_in[4];
    const float* Wkv  = (const float*)d_in[5];
    const float* bkv  = (const float*)d_in[6];
    const float* Wout = (const float*)d_in[7];
    const float* bout = (const float*)d_in[8];
    float* out = (float*)d_out;

    float *qp, *kvp, *offp, *attnp;
    cudaGetSymbolAddress((void**)&qp,    g_q);
    cudaGetSymbolAddress((void**)&kvp,   g_kv);
    cudaGetSymbolAddress((void**)&offp,  g_off);
    cudaGetSymbolAddress((void**)&attnp, g_attn);

    const int K = D_;
    gemm_tf32<<<dim3(2, MTOT / 128), 256>>>(x, Wq, bq, qp, K, D_, 0);
    sgemm_xwT<<<dim3(2, MTOT / 128), 256>>>(x, Woff, boff, offp, K, NH * NP * 2);
    gemm_tf32<<<dim3(4, MTOT / 128), 256>>>(x, Wkv, bkv, kvp, K, 2 * D_, 1);

    const int total_warps = B_ * NH * NTOK;
    deform_attn<<<(total_warps * 32) / 256, 256>>>(
        qp, (const float2*)kvp, offp, attnp);

    gemm_tf32<<<dim3(2, MTOT / 128), 256>>>(attnp, Wout, bout, out, K, D_, 0);
}